// round 11
// baseline (speedup 1.0000x reference)
#include <cuda_runtime.h>
#include <cuda_bf16.h>
#include <math_constants.h>
#include <cstdint>

#define N_SPIKES 16384
#define N_UNITS  256
#define N_NEIGHB 128
#define RANK     5
#define NCH      64
#define NCO      12
#define N_CAND   10
#define DDIM     60
#define OUT_COLS 61
#define CAP      2048
#define CPITCH   32          // cursor stride in ints = 128B (avoid L2 atomic line collisions)

typedef unsigned long long u64;

// packed fp32x2 FMA (sm_100+)
#define FMA2(d_, a_, b_, c_) \
    asm("fma.rn.f32x2 %0, %1, %2, %3;" : "=l"(d_) : "l"(a_), "l"(b_), "l"(c_))

__device__ __forceinline__ float lo32(u64 v) { return __int_as_float((int)(v & 0xffffffffull)); }
__device__ __forceinline__ float hi32(u64 v) { return __int_as_float((int)(v >> 32)); }

// Precomputed tables (device globals; no runtime allocation)
__device__ __align__(16) float g_H[N_NEIGHB * N_UNITS * DDIM];  // H[nid,u,:] = Coo_inv[nid] @ nu(nid,u)
__device__ float g_LLC[N_NEIGHB * N_UNITS];                     // logprop[u] - 0.5 * nu^T C nu
__device__ int   g_cursor[N_UNITS * CPITCH];                    // 128B-strided counters
__device__ __align__(16) int2 g_rec[N_UNITS * CAP];             // packed (spike, bits(q))

// ===========================================================================
// mma.sync helpers (arch-agnostic PTX; compiles for plain sm_103 target)
// ===========================================================================
__device__ __forceinline__ uint32_t smem_u32(const void* p) {
    uint32_t a;
    asm("{ .reg .u64 t; cvta.to.shared.u64 t, %1; cvt.u32.u64 %0, t; }" : "=r"(a) : "l"(p));
    return a;
}
__device__ __forceinline__ void ldsm_x4(uint32_t* r, uint32_t addr) {
    asm volatile("ldmatrix.sync.aligned.m8n8.x4.shared.b16 {%0,%1,%2,%3}, [%4];"
                 : "=r"(r[0]), "=r"(r[1]), "=r"(r[2]), "=r"(r[3]) : "r"(addr));
}
__device__ __forceinline__ void ldsm_x4_t(uint32_t* r, uint32_t addr) {
    asm volatile("ldmatrix.sync.aligned.m8n8.x4.trans.shared.b16 {%0,%1,%2,%3}, [%4];"
                 : "=r"(r[0]), "=r"(r[1]), "=r"(r[2]), "=r"(r[3]) : "r"(addr));
}
__device__ __forceinline__ void mma16816(float* c, const uint32_t* a, uint32_t b0, uint32_t b1) {
    asm volatile(
        "mma.sync.aligned.m16n8k16.row.col.f32.bf16.bf16.f32 "
        "{%0,%1,%2,%3}, {%4,%5,%6,%7}, {%8,%9}, {%0,%1,%2,%3};"
        : "+f"(c[0]), "+f"(c[1]), "+f"(c[2]), "+f"(c[3])
        : "r"(a[0]), "r"(a[1]), "r"(a[2]), "r"(a[3]), "r"(b0), "r"(b1));
}

// padded row-major tiles in dynamic smem. Row strides are ≡4 banks (mod 32):
// 8 consecutive rows' 16B ldmatrix segments cover all 32 banks -> conflict-free.
#define APITCH 264                       // bf16 elems per A row (528B)
#define BPITCH 72                        // bf16 elems per B row (144B)
#define SM_OBS 0
#define SM_A   64
#define SM_B   (SM_A + 128 * APITCH * 2) // 67648
#define SM_TOT (SM_B + 256 * BPITCH * 2) // 104512

// ---------------------------------------------------------------------------
// Kernel 1 (HMMA): grid 256 = (nid, unit-half). Per CTA:
//   A[128u x 256k] = [nuhi | nulo | nuhi | nulo]  (bf16 split, K segments of 64)
//   B[256k x 64d]  = [Chi  ; Chi  ; Clo  ; Clo ]  (stored k-row-major; C symmetric)
//   D[u,d] = A@B = C@nu in fp32 accum (bf16 products exact).
// 8 warps x (M16, N64): 128 mma.m16n8k16 per warp. Epilogue from accumulator
// registers: g_H float2 stores + G = H.nu (nu = hi+lo from A tile) -> LLC.
// Also zeroes cursors and `out`.
// ---------------------------------------------------------------------------
__global__ void __launch_bounds__(256) k_pre_mma(const float* __restrict__ mu,
                                                 const float* __restrict__ Cinv,
                                                 const int*   __restrict__ obs_ix,
                                                 const float* __restrict__ logprop,
                                                 float* __restrict__ out)
{
    extern __shared__ __align__(16) char sm[];
    const uint32_t smb = smem_u32(sm);
    const int nidv = blockIdx.x >> 1;
    const int half = blockIdx.x & 1;
    const int t    = threadIdx.x;
    const int wid  = t >> 5;
    const int lane = t & 31;
    int* obs_s = (int*)(sm + SM_OBS);
    __nv_bfloat16* A_sh = (__nv_bfloat16*)(sm + SM_A);
    __nv_bfloat16* B_sh = (__nv_bfloat16*)(sm + SM_B);

    if (blockIdx.x == 0) g_cursor[t * CPITCH] = 0;
    {   // zero the output (k_reduce accumulates with atomics)
        const int gidx = blockIdx.x * 256 + t;
        if (gidx < N_UNITS * OUT_COLS) out[gidx] = 0.f;
    }
    if (t < NCO) obs_s[t] = obs_ix[nidv * NCO + t];

    // zero-fill A+B (padding rows/cols must be 0.0, not stale NaN bits)
    {
        const float4 z = make_float4(0.f, 0.f, 0.f, 0.f);
        float4* p = reinterpret_cast<float4*>(sm + SM_A);
        for (int i = t; i < (SM_TOT - SM_A) / 16; i += 256) p[i] = z;
    }
    __syncthreads();

    // ---- fill A: unit u = t>>1 (local), each thread does 15 e-pairs ----
    {
        const int ul = t >> 1;
        const int jbase = (t & 1) * 15;
        const float* murow = mu + (half * 128 + ul) * (RANK * NCH);
        __nv_bfloat16* Arow = A_sh + ul * APITCH;
        #pragma unroll
        for (int j = 0; j < 15; j++) {
            const int e0 = 2 * (jbase + j), e1 = e0 + 1;
            const float v0 = murow[(e0 / NCO) * NCH + obs_s[e0 % NCO]];
            const float v1 = murow[(e1 / NCO) * NCH + obs_s[e1 % NCO]];
            const __nv_bfloat16 h0 = __float2bfloat16(v0);
            const __nv_bfloat16 h1 = __float2bfloat16(v1);
            const __nv_bfloat16 l0 = __float2bfloat16(v0 - __bfloat162float(h0));
            const __nv_bfloat16 l1 = __float2bfloat16(v1 - __bfloat162float(h1));
            const __nv_bfloat162 hh = __halves2bfloat162(h0, h1);
            const __nv_bfloat162 ll = __halves2bfloat162(l0, l1);
            *reinterpret_cast<__nv_bfloat162*>(Arow + e0)       = hh;
            *reinterpret_cast<__nv_bfloat162*>(Arow + 64 + e0)  = ll;
            *reinterpret_cast<__nv_bfloat162*>(Arow + 128 + e0) = hh;
            *reinterpret_cast<__nv_bfloat162*>(Arow + 192 + e0) = ll;
        }
    }
    // ---- fill B[k][d]: k = seg*64+e, value = split(C[e][d]) (C symmetric) ----
    {
        const float* C = Cinv + (size_t)nidv * (DDIM * DDIM);
        for (int i = t; i < 60 * 64; i += 256) {
            const int e = i >> 6, d = i & 63;
            const float v = (d < DDIM) ? C[e * DDIM + d] : 0.f;
            const __nv_bfloat16 h = __float2bfloat16(v);
            const __nv_bfloat16 l = __float2bfloat16(v - __bfloat162float(h));
            B_sh[(e)       * BPITCH + d] = h;
            B_sh[(64 + e)  * BPITCH + d] = h;
            B_sh[(128 + e) * BPITCH + d] = l;
            B_sh[(192 + e) * BPITCH + d] = l;
        }
    }
    __syncthreads();

    // ---- MMA mainloop: warp wid owns unit rows [wid*16, +16) ----
    float c0[4] = {0,0,0,0}, c1[4] = {0,0,0,0}, c2[4] = {0,0,0,0}, c3[4] = {0,0,0,0};
    float c4[4] = {0,0,0,0}, c5[4] = {0,0,0,0}, c6[4] = {0,0,0,0}, c7[4] = {0,0,0,0};
    {
        uint32_t aaddr = smb + SM_A + (uint32_t)((wid * 16 + (lane & 15)) * APITCH + ((lane >> 4) << 3)) * 2u;
        uint32_t baddr = smb + SM_B + (uint32_t)((lane & 15) * BPITCH + ((lane & 16) >> 1)) * 2u;
        #pragma unroll 4
        for (int k = 0; k < 16; k++) {
            uint32_t a[4];
            ldsm_x4(a, aaddr);
            uint32_t bb[4];
            ldsm_x4_t(bb, baddr);           // n-tiles 0,1
            mma16816(c0, a, bb[0], bb[1]);
            mma16816(c1, a, bb[2], bb[3]);
            ldsm_x4_t(bb, baddr + 32);      // n-tiles 2,3
            mma16816(c2, a, bb[0], bb[1]);
            mma16816(c3, a, bb[2], bb[3]);
            ldsm_x4_t(bb, baddr + 64);      // n-tiles 4,5
            mma16816(c4, a, bb[0], bb[1]);
            mma16816(c5, a, bb[2], bb[3]);
            ldsm_x4_t(bb, baddr + 96);      // n-tiles 6,7
            mma16816(c6, a, bb[0], bb[1]);
            mma16816(c7, a, bb[2], bb[3]);
            aaddr += 32;                    // +16 bf16 in k
            baddr += 16 * BPITCH * 2;       // +16 k-rows
        }
    }

    // ---- epilogue: lane (g,tig) holds rows g,g+8 cols {8j+2tig, +1} ----
    {
        const int g = lane >> 2, tig = lane & 3;
        const int ul0 = wid * 16 + g;            // local unit rows
        const int u0 = half * 128 + ul0;
        const int u1 = u0 + 8;
        float* H0 = g_H + (size_t)(nidv * N_UNITS + u0) * DDIM;
        float* H1 = g_H + (size_t)(nidv * N_UNITS + u1) * DDIM;
        const __nv_bfloat16* Ar0 = A_sh + ul0 * APITCH;
        const __nv_bfloat16* Ar1 = Ar0 + 8 * APITCH;
        float G0 = 0.f, G1 = 0.f;
        float* cs[8] = {c0, c1, c2, c3, c4, c5, c6, c7};
        #pragma unroll
        for (int j = 0; j < 8; j++) {
            const int col = 8 * j + 2 * tig;
            if (col < DDIM) {                     // skips only j==7, tig>=2
                *reinterpret_cast<float2*>(H0 + col) = make_float2(cs[j][0], cs[j][1]);
                *reinterpret_cast<float2*>(H1 + col) = make_float2(cs[j][2], cs[j][3]);
                const float2 nh0 = __bfloat1622float2(*reinterpret_cast<const __nv_bfloat162*>(Ar0 + col));
                const float2 nl0 = __bfloat1622float2(*reinterpret_cast<const __nv_bfloat162*>(Ar0 + 64 + col));
                const float2 nh1 = __bfloat1622float2(*reinterpret_cast<const __nv_bfloat162*>(Ar1 + col));
                const float2 nl1 = __bfloat1622float2(*reinterpret_cast<const __nv_bfloat162*>(Ar1 + 64 + col));
                G0 = fmaf(cs[j][0], nh0.x + nl0.x, G0);
                G0 = fmaf(cs[j][1], nh0.y + nl0.y, G0);
                G1 = fmaf(cs[j][2], nh1.x + nl1.x, G1);
                G1 = fmaf(cs[j][3], nh1.y + nl1.y, G1);
            }
        }
        G0 += __shfl_xor_sync(0xffffffffu, G0, 1);
        G0 += __shfl_xor_sync(0xffffffffu, G0, 2);
        G1 += __shfl_xor_sync(0xffffffffu, G1, 1);
        G1 += __shfl_xor_sync(0xffffffffu, G1, 2);
        if (tig == 0) {
            g_LLC[nidv * N_UNITS + u0] = logprop[u0] - 0.5f * G0;
            g_LLC[nidv * N_UNITS + u1] = logprop[u1] - 0.5f * G1;
        }
    }
}

// ---------------------------------------------------------------------------
// Kernel 2: per-spike responsibilities. One warp per spike. (unchanged, R9)
// ---------------------------------------------------------------------------
__global__ void __launch_bounds__(256) k_main(const float* __restrict__ features,
                                              const int*   __restrict__ cands,
                                              const int*   __restrict__ nid,
                                              const float* __restrict__ noise_lp)
{
    const int t    = threadIdx.x;
    const int warp = t >> 5;
    const int lane = t & 31;
    const int s    = blockIdx.x * 8 + warp;
    const int li   = lane < 30 ? lane : 29;

    const float nlp = __ldg(noise_lp);
    const u64* xf2 = reinterpret_cast<const u64*>(features + (size_t)s * DDIM);
    u64 x2 = __ldg(&xf2[li]);
    if (lane >= 30) x2 = 0ull;

    const int nidv  = __ldg(&nid[s]);
    const int pbase = nidv * N_UNITS;
    const int ucached = (lane < N_CAND) ? __ldg(&cands[s * N_CAND + lane]) : 0;
    const float llc_l = (lane < N_CAND) ? g_LLC[pbase + ucached] : 0.f;

    u64 h2[N_CAND];
    #pragma unroll
    for (int c = 0; c < N_CAND; c++) {
        const int u = __shfl_sync(0xffffffffu, ucached, c);
        const u64* H2 = reinterpret_cast<const u64*>(g_H + (size_t)(pbase + u) * DDIM);
        h2[c] = __ldg(&H2[li]);
    }

    float acc[N_CAND];
    #pragma unroll
    for (int c = 0; c < N_CAND; c++) {
        u64 p2 = 0ull;
        FMA2(p2, x2, h2[c], p2);
        acc[c] = lo32(p2) + hi32(p2);
    }

    #pragma unroll
    for (int o = 16; o; o >>= 1) {
        #pragma unroll
        for (int c = 0; c < N_CAND; c++)
            acc[c] += __shfl_xor_sync(0xffffffffu, acc[c], o);
    }

    float myp = acc[0];
    #pragma unroll
    for (int c = 1; c < N_CAND; c++)
        if (lane == c) myp = acc[c];

    float myll = -CUDART_INF_F;
    if (lane < N_CAND) myll = llc_l + myp;
    if (lane == N_CAND) myll = nlp;

    float mx = myll;
    #pragma unroll
    for (int o = 16; o; o >>= 1) mx = fmaxf(mx, __shfl_xor_sync(0xffffffffu, mx, o));
    const float ex = (lane <= N_CAND) ? __expf(myll - mx) : 0.f;
    float sm = ex;
    #pragma unroll
    for (int o = 16; o; o >>= 1) sm += __shfl_xor_sync(0xffffffffu, sm, o);

    if (lane < N_CAND) {
        const float qv = ex / sm;
        const int u = ucached;
        const int pos = atomicAdd(&g_cursor[u * CPITCH], 1);
        if (pos < CAP) {
            g_rec[u * CAP + pos] = make_int2(s, __float_as_int(qv));
        }
    }
}

// ---------------------------------------------------------------------------
// Kernel 3: per-unit weighted reduction, 4 blocks per unit. (unchanged, R9)
// ---------------------------------------------------------------------------
__global__ void __launch_bounds__(256) k_reduce(const float* __restrict__ features,
                                                float* __restrict__ out)
{
    const int u    = blockIdx.x >> 2;
    const int part = blockIdx.x & 3;
    const int t    = threadIdx.x;
    const int warp = t >> 5;
    const int lane = t & 31;
    const int li   = lane < 30 ? lane : 29;
    const bool act = lane < 30;

    int cnt = g_cursor[u * CPITCH];
    if (cnt > CAP) cnt = CAP;

    const int base = u * CAP;
    const int slot = part * 8 + warp;
    u64 a2 = 0ull;
    float ac = 0.f;

    for (int eb = slot * 8; eb < cnt; eb += 32 * 8) {
        int   n[8];
        float q[8];
        #pragma unroll
        for (int i = 0; i < 8; i++) {
            const bool v = (eb + i) < cnt;
            const int2 rec = v ? g_rec[base + eb + i] : make_int2(0, 0);
            n[i] = rec.x;
            q[i] = v ? __int_as_float(rec.y) : 0.f;
        }
        u64 f2[8];
        #pragma unroll
        for (int i = 0; i < 8; i++) {
            const u64* xf2 = reinterpret_cast<const u64*>(features + (size_t)n[i] * DDIM);
            f2[i] = __ldg(&xf2[li]);
        }
        #pragma unroll
        for (int i = 0; i < 8; i++) {
            const unsigned qb = (unsigned)__float_as_int(q[i]);
            const u64 q2 = ((u64)qb << 32) | qb;
            FMA2(a2, q2, f2[i], a2);
            ac += q[i];
        }
    }

    __shared__ float sh[8][OUT_COLS];
    if (act) {
        sh[warp][1 + 2 * lane] = lo32(a2);
        sh[warp][2 + 2 * lane] = hi32(a2);
    }
    if (lane == 0) sh[warp][0] = ac;
    __syncthreads();

    if (t < OUT_COLS) {
        float sum = 0.f;
        #pragma unroll
        for (int w2 = 0; w2 < 8; w2++) sum += sh[w2][t];
        atomicAdd(&out[u * OUT_COLS + t], sum);
    }
}

// ---------------------------------------------------------------------------
// Input order: features, mu, Coo_inv, Coo_logdet, log_proportions,
//              noise_log_prop, cands, nid, obs_ix
// ---------------------------------------------------------------------------
extern "C" void kernel_launch(void* const* d_in, const int* in_sizes, int n_in,
                              void* d_out, int out_size)
{
    const float* features  = (const float*)d_in[0];
    const float* mu        = (const float*)d_in[1];
    const float* Coo_inv   = (const float*)d_in[2];
    const float* logprop   = (const float*)d_in[4];
    const float* noise_lp  = (const float*)d_in[5];
    const int*   cands     = (const int*)d_in[6];
    const int*   nidp      = (const int*)d_in[7];
    const int*   obs_ix    = (const int*)d_in[8];
    float* out = (float*)d_out;

    static int smem_set = 0;
    if (!smem_set) {
        cudaFuncSetAttribute(k_pre_mma, cudaFuncAttributeMaxDynamicSharedMemorySize, SM_TOT);
        smem_set = 1;
    }
    k_pre_mma<<<N_NEIGHB * 2, 256, SM_TOT>>>(mu, Coo_inv, obs_ix, logprop, out);
    k_main<<<N_SPIKES / 8, 256>>>(features, cands, nidp, noise_lp);
    k_reduce<<<N_UNITS * 4, 256>>>(features, out);
}

// round 12
// speedup vs baseline: 1.1079x; 1.1079x over previous
#include <cuda_runtime.h>
#include <cuda_bf16.h>
#include <math_constants.h>
#include <cstdint>

#define N_SPIKES 16384
#define N_UNITS  256
#define N_NEIGHB 128
#define RANK     5
#define NCH      64
#define NCO      12
#define N_CAND   10
#define DDIM     60
#define OUT_COLS 61
#define CAP      2048
#define CPITCH   32          // cursor stride in ints = 128B (avoid L2 atomic line collisions)

typedef unsigned long long u64;

// packed fp32x2 FMA (sm_100+)
#define FMA2(d_, a_, b_, c_) \
    asm("fma.rn.f32x2 %0, %1, %2, %3;" : "=l"(d_) : "l"(a_), "l"(b_), "l"(c_))

__device__ __forceinline__ float lo32(u64 v) { return __int_as_float((int)(v & 0xffffffffull)); }
__device__ __forceinline__ float hi32(u64 v) { return __int_as_float((int)(v >> 32)); }

// Precomputed tables (device globals; no runtime allocation)
__device__ __align__(16) float g_H[N_NEIGHB * N_UNITS * DDIM];  // H[nid,u,:] = Coo_inv[nid] @ nu(nid,u)
__device__ float g_LLC[N_NEIGHB * N_UNITS];                     // logprop[u] - 0.5 * nu^T C nu
__device__ int   g_cursor[N_UNITS * CPITCH];                    // 128B-strided counters
__device__ __align__(16) int2 g_rec[N_UNITS * CAP];             // packed (spike, bits(q))

// ===========================================================================
// mma.sync helpers (arch-agnostic PTX; compiles for plain sm_103 target)
// ===========================================================================
__device__ __forceinline__ uint32_t smem_u32(const void* p) {
    uint32_t a;
    asm("{ .reg .u64 t; cvta.to.shared.u64 t, %1; cvt.u32.u64 %0, t; }" : "=r"(a) : "l"(p));
    return a;
}
__device__ __forceinline__ void ldsm_x4(uint32_t* r, uint32_t addr) {
    asm volatile("ldmatrix.sync.aligned.m8n8.x4.shared.b16 {%0,%1,%2,%3}, [%4];"
                 : "=r"(r[0]), "=r"(r[1]), "=r"(r[2]), "=r"(r[3]) : "r"(addr));
}
__device__ __forceinline__ void ldsm_x4_t(uint32_t* r, uint32_t addr) {
    asm volatile("ldmatrix.sync.aligned.m8n8.x4.trans.shared.b16 {%0,%1,%2,%3}, [%4];"
                 : "=r"(r[0]), "=r"(r[1]), "=r"(r[2]), "=r"(r[3]) : "r"(addr));
}
__device__ __forceinline__ void mma16816(float* c, const uint32_t* a, uint32_t b0, uint32_t b1) {
    asm volatile(
        "mma.sync.aligned.m16n8k16.row.col.f32.bf16.bf16.f32 "
        "{%0,%1,%2,%3}, {%4,%5,%6,%7}, {%8,%9}, {%0,%1,%2,%3};"
        : "+f"(c[0]), "+f"(c[1]), "+f"(c[2]), "+f"(c[3])
        : "r"(a[0]), "r"(a[1]), "r"(a[2]), "r"(a[3]), "r"(b0), "r"(b1));
}

// padded row-major tiles in dynamic smem. Row strides ≡4 banks (mod 32):
// 8 consecutive rows' 16B ldmatrix segments cover all 32 banks -> conflict-free.
#define APITCH 136                        // bf16 per A row (272B): [hi(60)|pad|lo(60)|pad]
#define BPITCH 72                         // bf16 per B row (144B)
#define SM_OBS 0
#define SM_A   64
#define SM_B1  (SM_A + 128 * APITCH * 2)  // 34880 : B1 = [Chi ; Chi] (128 k-rows)
#define SM_B2  (SM_B1 + 128 * BPITCH * 2) // 53312 : B2 = [Clo] (64 k-rows)
#define SM_TOT (SM_B2 + 64 * BPITCH * 2)  // 62528

// ---------------------------------------------------------------------------
// Kernel 1 (HMMA): grid 256 = (nid, unit-half). 3-term bf16-split GEMM:
//   D = Chi*hi + Chi*lo + Clo*hi  (drops O(2^-32) Clo*lo term)
//   pass1: A[128u x 128k]=[hi|lo] @ B1[128k x 64d]=[Chi;Chi]   (8 k-iters)
//   pass2: A[:, 0:64]=hi          @ B2[ 64k x 64d]=[Clo]       (4 k-iters)
// 8 warps x (M16,N64). All 5 ldsm per iter into SEPARATE buffers, issued
// up-front (no WAR serialization). 61KB smem -> 3 CTAs/SM, single wave.
// Epilogue: accumulator regs -> g_H float2 stores + G = H.nu -> LLC.
// Also zeroes cursors and `out`.
// ---------------------------------------------------------------------------
__global__ void __launch_bounds__(256) k_pre_mma(const float* __restrict__ mu,
                                                 const float* __restrict__ Cinv,
                                                 const int*   __restrict__ obs_ix,
                                                 const float* __restrict__ logprop,
                                                 float* __restrict__ out)
{
    extern __shared__ __align__(16) char sm[];
    const uint32_t smb = smem_u32(sm);
    const int nidv = blockIdx.x >> 1;
    const int half = blockIdx.x & 1;
    const int t    = threadIdx.x;
    const int wid  = t >> 5;
    const int lane = t & 31;
    int* obs_s = (int*)(sm + SM_OBS);
    __nv_bfloat16* A_sh  = (__nv_bfloat16*)(sm + SM_A);
    __nv_bfloat16* B1_sh = (__nv_bfloat16*)(sm + SM_B1);
    __nv_bfloat16* B2_sh = (__nv_bfloat16*)(sm + SM_B2);

    if (blockIdx.x == 0) g_cursor[t * CPITCH] = 0;
    {   // zero the output (k_reduce accumulates with atomics)
        const int gidx = blockIdx.x * 256 + t;
        if (gidx < N_UNITS * OUT_COLS) out[gidx] = 0.f;
    }
    if (t < NCO) obs_s[t] = obs_ix[nidv * NCO + t];

    // zero-fill tiles (padding must be 0.0)
    {
        const float4 z = make_float4(0.f, 0.f, 0.f, 0.f);
        float4* p = reinterpret_cast<float4*>(sm + SM_A);
        for (int i = t; i < (SM_TOT - SM_A) / 16; i += 256) p[i] = z;
    }
    __syncthreads();

    // ---- fill A: unit ul = t>>1, 15 e-pairs per thread ----
    {
        const int ul = t >> 1;
        const int jbase = (t & 1) * 15;
        const float* murow = mu + (half * 128 + ul) * (RANK * NCH);
        __nv_bfloat16* Arow = A_sh + ul * APITCH;
        #pragma unroll
        for (int j = 0; j < 15; j++) {
            const int e0 = 2 * (jbase + j), e1 = e0 + 1;
            const float v0 = murow[(e0 / NCO) * NCH + obs_s[e0 % NCO]];
            const float v1 = murow[(e1 / NCO) * NCH + obs_s[e1 % NCO]];
            const __nv_bfloat16 h0 = __float2bfloat16(v0);
            const __nv_bfloat16 h1 = __float2bfloat16(v1);
            const __nv_bfloat16 l0 = __float2bfloat16(v0 - __bfloat162float(h0));
            const __nv_bfloat16 l1 = __float2bfloat16(v1 - __bfloat162float(h1));
            *reinterpret_cast<__nv_bfloat162*>(Arow + e0)      = __halves2bfloat162(h0, h1);
            *reinterpret_cast<__nv_bfloat162*>(Arow + 64 + e0) = __halves2bfloat162(l0, l1);
        }
    }
    // ---- fill B1/B2: k-row-major, C symmetric ----
    {
        const float* C = Cinv + (size_t)nidv * (DDIM * DDIM);
        for (int i = t; i < 60 * 64; i += 256) {
            const int e = i >> 6, d = i & 63;
            const float v = (d < DDIM) ? C[e * DDIM + d] : 0.f;
            const __nv_bfloat16 h = __float2bfloat16(v);
            const __nv_bfloat16 l = __float2bfloat16(v - __bfloat162float(h));
            B1_sh[e        * BPITCH + d] = h;
            B1_sh[(64 + e) * BPITCH + d] = h;
            B2_sh[e        * BPITCH + d] = l;
        }
    }
    __syncthreads();

    // ---- MMA mainloop: warp wid owns unit rows [wid*16, +16) ----
    float c0[4] = {0,0,0,0}, c1[4] = {0,0,0,0}, c2[4] = {0,0,0,0}, c3[4] = {0,0,0,0};
    float c4[4] = {0,0,0,0}, c5[4] = {0,0,0,0}, c6[4] = {0,0,0,0}, c7[4] = {0,0,0,0};
    {
        const uint32_t a0addr = smb + SM_A +
            (uint32_t)((wid * 16 + (lane & 15)) * APITCH + ((lane >> 4) << 3)) * 2u;
        const uint32_t brow = (uint32_t)((lane & 15) * BPITCH + ((lane & 16) >> 1)) * 2u;

        uint32_t aaddr = a0addr;
        uint32_t baddr = smb + SM_B1 + brow;
        #pragma unroll
        for (int k = 0; k < 8; k++) {       // pass 1: A[hi|lo] @ [Chi;Chi]
            uint32_t a[4], b0[4], b1[4], b2[4], b3[4];
            ldsm_x4(a, aaddr);
            ldsm_x4_t(b0, baddr);
            ldsm_x4_t(b1, baddr + 32);
            ldsm_x4_t(b2, baddr + 64);
            ldsm_x4_t(b3, baddr + 96);
            mma16816(c0, a, b0[0], b0[1]);
            mma16816(c1, a, b0[2], b0[3]);
            mma16816(c2, a, b1[0], b1[1]);
            mma16816(c3, a, b1[2], b1[3]);
            mma16816(c4, a, b2[0], b2[1]);
            mma16816(c5, a, b2[2], b2[3]);
            mma16816(c6, a, b3[0], b3[1]);
            mma16816(c7, a, b3[2], b3[3]);
            aaddr += 32;
            baddr += 16 * BPITCH * 2;
        }
        aaddr = a0addr;                      // pass 2: A[hi] @ [Clo]
        baddr = smb + SM_B2 + brow;
        #pragma unroll
        for (int k = 0; k < 4; k++) {
            uint32_t a[4], b0[4], b1[4], b2[4], b3[4];
            ldsm_x4(a, aaddr);
            ldsm_x4_t(b0, baddr);
            ldsm_x4_t(b1, baddr + 32);
            ldsm_x4_t(b2, baddr + 64);
            ldsm_x4_t(b3, baddr + 96);
            mma16816(c0, a, b0[0], b0[1]);
            mma16816(c1, a, b0[2], b0[3]);
            mma16816(c2, a, b1[0], b1[1]);
            mma16816(c3, a, b1[2], b1[3]);
            mma16816(c4, a, b2[0], b2[1]);
            mma16816(c5, a, b2[2], b2[3]);
            mma16816(c6, a, b3[0], b3[1]);
            mma16816(c7, a, b3[2], b3[3]);
            aaddr += 32;
            baddr += 16 * BPITCH * 2;
        }
    }

    // ---- epilogue: lane (g,tig) holds rows g,g+8 cols {8j+2tig, +1} ----
    {
        const int g = lane >> 2, tig = lane & 3;
        const int ul0 = wid * 16 + g;
        const int u0 = half * 128 + ul0;
        const int u1 = u0 + 8;
        float* H0 = g_H + (size_t)(nidv * N_UNITS + u0) * DDIM;
        float* H1 = g_H + (size_t)(nidv * N_UNITS + u1) * DDIM;
        const __nv_bfloat16* Ar0 = A_sh + ul0 * APITCH;
        const __nv_bfloat16* Ar1 = Ar0 + 8 * APITCH;
        float G0 = 0.f, G1 = 0.f;
        float* cs[8] = {c0, c1, c2, c3, c4, c5, c6, c7};
        #pragma unroll
        for (int j = 0; j < 8; j++) {
            const int col = 8 * j + 2 * tig;
            if (col < DDIM) {                 // skips only j==7, tig>=2
                *reinterpret_cast<float2*>(H0 + col) = make_float2(cs[j][0], cs[j][1]);
                *reinterpret_cast<float2*>(H1 + col) = make_float2(cs[j][2], cs[j][3]);
                const float2 nh0 = __bfloat1622float2(*reinterpret_cast<const __nv_bfloat162*>(Ar0 + col));
                const float2 nl0 = __bfloat1622float2(*reinterpret_cast<const __nv_bfloat162*>(Ar0 + 64 + col));
                const float2 nh1 = __bfloat1622float2(*reinterpret_cast<const __nv_bfloat162*>(Ar1 + col));
                const float2 nl1 = __bfloat1622float2(*reinterpret_cast<const __nv_bfloat162*>(Ar1 + 64 + col));
                G0 = fmaf(cs[j][0], nh0.x + nl0.x, G0);
                G0 = fmaf(cs[j][1], nh0.y + nl0.y, G0);
                G1 = fmaf(cs[j][2], nh1.x + nl1.x, G1);
                G1 = fmaf(cs[j][3], nh1.y + nl1.y, G1);
            }
        }
        G0 += __shfl_xor_sync(0xffffffffu, G0, 1);
        G0 += __shfl_xor_sync(0xffffffffu, G0, 2);
        G1 += __shfl_xor_sync(0xffffffffu, G1, 1);
        G1 += __shfl_xor_sync(0xffffffffu, G1, 2);
        if (tig == 0) {
            g_LLC[nidv * N_UNITS + u0] = logprop[u0] - 0.5f * G0;
            g_LLC[nidv * N_UNITS + u1] = logprop[u1] - 0.5f * G1;
        }
    }
}

// ---------------------------------------------------------------------------
// Kernel 2: per-spike responsibilities. One warp per spike. (unchanged, R9)
// ---------------------------------------------------------------------------
__global__ void __launch_bounds__(256) k_main(const float* __restrict__ features,
                                              const int*   __restrict__ cands,
                                              const int*   __restrict__ nid,
                                              const float* __restrict__ noise_lp)
{
    const int t    = threadIdx.x;
    const int warp = t >> 5;
    const int lane = t & 31;
    const int s    = blockIdx.x * 8 + warp;
    const int li   = lane < 30 ? lane : 29;

    const float nlp = __ldg(noise_lp);
    const u64* xf2 = reinterpret_cast<const u64*>(features + (size_t)s * DDIM);
    u64 x2 = __ldg(&xf2[li]);
    if (lane >= 30) x2 = 0ull;

    const int nidv  = __ldg(&nid[s]);
    const int pbase = nidv * N_UNITS;
    const int ucached = (lane < N_CAND) ? __ldg(&cands[s * N_CAND + lane]) : 0;
    const float llc_l = (lane < N_CAND) ? g_LLC[pbase + ucached] : 0.f;

    u64 h2[N_CAND];
    #pragma unroll
    for (int c = 0; c < N_CAND; c++) {
        const int u = __shfl_sync(0xffffffffu, ucached, c);
        const u64* H2 = reinterpret_cast<const u64*>(g_H + (size_t)(pbase + u) * DDIM);
        h2[c] = __ldg(&H2[li]);
    }

    float acc[N_CAND];
    #pragma unroll
    for (int c = 0; c < N_CAND; c++) {
        u64 p2 = 0ull;
        FMA2(p2, x2, h2[c], p2);
        acc[c] = lo32(p2) + hi32(p2);
    }

    #pragma unroll
    for (int o = 16; o; o >>= 1) {
        #pragma unroll
        for (int c = 0; c < N_CAND; c++)
            acc[c] += __shfl_xor_sync(0xffffffffu, acc[c], o);
    }

    float myp = acc[0];
    #pragma unroll
    for (int c = 1; c < N_CAND; c++)
        if (lane == c) myp = acc[c];

    float myll = -CUDART_INF_F;
    if (lane < N_CAND) myll = llc_l + myp;
    if (lane == N_CAND) myll = nlp;

    float mx = myll;
    #pragma unroll
    for (int o = 16; o; o >>= 1) mx = fmaxf(mx, __shfl_xor_sync(0xffffffffu, mx, o));
    const float ex = (lane <= N_CAND) ? __expf(myll - mx) : 0.f;
    float sm = ex;
    #pragma unroll
    for (int o = 16; o; o >>= 1) sm += __shfl_xor_sync(0xffffffffu, sm, o);

    if (lane < N_CAND) {
        const float qv = ex / sm;
        const int u = ucached;
        const int pos = atomicAdd(&g_cursor[u * CPITCH], 1);
        if (pos < CAP) {
            g_rec[u * CAP + pos] = make_int2(s, __float_as_int(qv));
        }
    }
}

// ---------------------------------------------------------------------------
// Kernel 3: per-unit weighted reduction, 4 blocks per unit. (unchanged, R9)
// ---------------------------------------------------------------------------
__global__ void __launch_bounds__(256) k_reduce(const float* __restrict__ features,
                                                float* __restrict__ out)
{
    const int u    = blockIdx.x >> 2;
    const int part = blockIdx.x & 3;
    const int t    = threadIdx.x;
    const int warp = t >> 5;
    const int lane = t & 31;
    const int li   = lane < 30 ? lane : 29;
    const bool act = lane < 30;

    int cnt = g_cursor[u * CPITCH];
    if (cnt > CAP) cnt = CAP;

    const int base = u * CAP;
    const int slot = part * 8 + warp;
    u64 a2 = 0ull;
    float ac = 0.f;

    for (int eb = slot * 8; eb < cnt; eb += 32 * 8) {
        int   n[8];
        float q[8];
        #pragma unroll
        for (int i = 0; i < 8; i++) {
            const bool v = (eb + i) < cnt;
            const int2 rec = v ? g_rec[base + eb + i] : make_int2(0, 0);
            n[i] = rec.x;
            q[i] = v ? __int_as_float(rec.y) : 0.f;
        }
        u64 f2[8];
        #pragma unroll
        for (int i = 0; i < 8; i++) {
            const u64* xf2 = reinterpret_cast<const u64*>(features + (size_t)n[i] * DDIM);
            f2[i] = __ldg(&xf2[li]);
        }
        #pragma unroll
        for (int i = 0; i < 8; i++) {
            const unsigned qb = (unsigned)__float_as_int(q[i]);
            const u64 q2 = ((u64)qb << 32) | qb;
            FMA2(a2, q2, f2[i], a2);
            ac += q[i];
        }
    }

    __shared__ float sh[8][OUT_COLS];
    if (act) {
        sh[warp][1 + 2 * lane] = lo32(a2);
        sh[warp][2 + 2 * lane] = hi32(a2);
    }
    if (lane == 0) sh[warp][0] = ac;
    __syncthreads();

    if (t < OUT_COLS) {
        float sum = 0.f;
        #pragma unroll
        for (int w2 = 0; w2 < 8; w2++) sum += sh[w2][t];
        atomicAdd(&out[u * OUT_COLS + t], sum);
    }
}

// ---------------------------------------------------------------------------
// Input order: features, mu, Coo_inv, Coo_logdet, log_proportions,
//              noise_log_prop, cands, nid, obs_ix
// ---------------------------------------------------------------------------
extern "C" void kernel_launch(void* const* d_in, const int* in_sizes, int n_in,
                              void* d_out, int out_size)
{
    const float* features  = (const float*)d_in[0];
    const float* mu        = (const float*)d_in[1];
    const float* Coo_inv   = (const float*)d_in[2];
    const float* logprop   = (const float*)d_in[4];
    const float* noise_lp  = (const float*)d_in[5];
    const int*   cands     = (const int*)d_in[6];
    const int*   nidp      = (const int*)d_in[7];
    const int*   obs_ix    = (const int*)d_in[8];
    float* out = (float*)d_out;

    static int smem_set = 0;
    if (!smem_set) {
        cudaFuncSetAttribute(k_pre_mma, cudaFuncAttributeMaxDynamicSharedMemorySize, SM_TOT);
        smem_set = 1;
    }
    k_pre_mma<<<N_NEIGHB * 2, 256, SM_TOT>>>(mu, Coo_inv, obs_ix, logprop, out);
    k_main<<<N_SPIKES / 8, 256>>>(features, cands, nidp, noise_lp);
    k_reduce<<<N_UNITS * 4, 256>>>(features, out);
}

// round 13
// speedup vs baseline: 1.1689x; 1.0550x over previous
#include <cuda_runtime.h>
#include <math_constants.h>

#define N_SPIKES 16384
#define N_UNITS  256
#define N_NEIGHB 128
#define RANK     5
#define NCH      64
#define NCO      12
#define N_CAND   10
#define DDIM     60
#define OUT_COLS 61
#define CAP      2048
#define CPITCH   32          // cursor stride in ints = 128B (avoid L2 atomic line collisions)
#define CSH_PITCH 68         // words; lane-l LDS.128 hits banks 4l..4l+3: conflict-free per phase
#define CSH_ROWS  64         // rows 60..63 are zero padding so lane 28..31 loads are valid
#define RSPLIT   8           // k_reduce blocks per unit

typedef unsigned long long u64;

// packed fp32x2 FMA (sm_100+): d = a*b + c elementwise on (lo,hi) pairs
#define FMA2(d_, a_, b_, c_) \
    asm("fma.rn.f32x2 %0, %1, %2, %3;" : "=l"(d_) : "l"(a_), "l"(b_), "l"(c_))

__device__ __forceinline__ float lo32(u64 v) { return __int_as_float((int)(v & 0xffffffffull)); }
__device__ __forceinline__ float hi32(u64 v) { return __int_as_float((int)(v >> 32)); }

// Precomputed tables (device globals; no runtime allocation)
__device__ __align__(16) float g_H[N_NEIGHB * N_UNITS * DDIM];  // H[nid,u,:] = Coo_inv[nid] @ nu(nid,u)
__device__ float g_LLC[N_NEIGHB * N_UNITS];                     // logprop[u] - 0.5 * nu^T C nu
__device__ int   g_cursor[N_UNITS * CPITCH];                    // 128B-strided counters
__device__ __align__(16) int2 g_rec[N_UNITS * CAP];             // packed (spike, bits(q))

// ---------------------------------------------------------------------------
// Kernel 1: per-(nid, unit-half) precompute of H and LLC.
// grid = 256, block = 512 (16 warps): block b -> nid = b>>1, units
// [(b&1)*128, +128). Each warp: 8 units in 2 passes of 4.
// ALL nu gathers hoisted above the C fill (their L2 latency overlaps the
// fill's); obs indices loaded per-thread from global (no sync dependency);
// pass loops are gather-free. C in shared, pitch 68 / 64 zero-padded rows
// (all LDS.128 valid + unconditional). Also zeroes cursors and `out`.
// ---------------------------------------------------------------------------
__global__ void __launch_bounds__(512, 2) k_pre(const float* __restrict__ mu,
                                                const float* __restrict__ Cinv,
                                                const int*   __restrict__ obs_ix,
                                                const float* __restrict__ logprop,
                                                float* __restrict__ out)
{
    __shared__ __align__(16) float Csh[CSH_ROWS * CSH_PITCH];
    __shared__ __align__(16) float nub[16][8][64];   // [warp][unit-slot][e]

    const int nidv = blockIdx.x >> 1;
    const int half = blockIdx.x & 1;
    const int t    = threadIdx.x;
    const int warp = t >> 5;
    const int lane = t & 31;

    if (blockIdx.x == 0 && t < N_UNITS) g_cursor[t * CPITCH] = 0;

    // zero the output (k_reduce accumulates into it with atomics)
    {
        const int gidx = blockIdx.x * 512 + t;
        if (gidx < N_UNITS * OUT_COLS) out[gidx] = 0.f;
    }

    const int d0 = lane;            // always valid (< 60)
    const int d1 = lane + 32;       // real dim only when lane < 28; rows 60-63 are zeros
    const bool has1 = (d1 < DDIM);
    const int r0 = d0 / NCO, k0 = d0 % NCO;
    const int r1 = has1 ? (d1 / NCO) : 0;
    const int k1 = has1 ? (d1 % NCO) : 0;

    // per-thread obs loads (L1/L2-resident; removes the obs staging sync)
    const int o0 = __ldg(&obs_ix[nidv * NCO + k0]);
    const int o1 = has1 ? __ldg(&obs_ix[nidv * NCO + k1]) : 0;

    // hoisted nu gathers for all 8 unit-slots (both passes); latency overlaps
    // the C fill below
    const int ubase0 = half * 128 + warp * 8;
    float nv0[8], nv1[8];
    #pragma unroll
    for (int s8 = 0; s8 < 8; s8++) {
        const int u = ubase0 + s8;
        nv0[s8] = __ldg(&mu[u * (RANK * NCH) + r0 * NCH + o0]);
        nv1[s8] = has1 ? __ldg(&mu[u * (RANK * NCH) + r1 * NCH + o1]) : 0.f;
    }

    // C fill with float4 copies: each row is exactly 15 float4, no row crossing.
    {
        const float4* C4 = reinterpret_cast<const float4*>(Cinv + (size_t)nidv * (DDIM * DDIM));
        for (int f = t; f < DDIM * (DDIM / 4); f += 512) {
            const int r = f / 15, c4 = f % 15;
            reinterpret_cast<float4*>(Csh + r * CSH_PITCH)[c4] = C4[f];
        }
        // zero pad rows 60..63 (first 15 float4 of each, the only part read)
        if (t < 60) {
            const int r = 60 + t / 15, c4 = t % 15;
            reinterpret_cast<float4*>(Csh + r * CSH_PITCH)[c4] = make_float4(0.f, 0.f, 0.f, 0.f);
        }
    }

    // stage nu into shared (warp-private region)
    #pragma unroll
    for (int s8 = 0; s8 < 8; s8++) {
        nub[warp][s8][d0] = nv0[s8];
        if (has1) nub[warp][s8][d1] = nv1[s8];
    }
    __syncthreads();

    const ulonglong2* Crow0 = reinterpret_cast<const ulonglong2*>(Csh + d0 * CSH_PITCH);
    const ulonglong2* Crow1 = reinterpret_cast<const ulonglong2*>(Csh + d1 * CSH_PITCH);

    #pragma unroll
    for (int pass = 0; pass < 2; pass++) {
        const int sb = pass * 4;
        const int ubase = ubase0 + sb;

        u64 acc0[4], acc1[4];
        #pragma unroll
        for (int j = 0; j < 4; j++) { acc0[j] = 0ull; acc1[j] = 0ull; }

        #pragma unroll 5
        for (int q = 0; q < DDIM / 4; q++) {       // one float4 group (2 e-pairs) per iter
            const ulonglong2 c0 = Crow0[q];        // LDS.128, unconditional
            const ulonglong2 c1 = Crow1[q];        // LDS.128, unconditional (zeros for d1>=60)
            ulonglong2 n[4];
            #pragma unroll
            for (int j = 0; j < 4; j++)
                n[j] = reinterpret_cast<const ulonglong2*>(nub[warp][sb + j])[q];  // broadcast
            #pragma unroll
            for (int j = 0; j < 4; j++) {
                FMA2(acc0[j], c0.x, n[j].x, acc0[j]);
                FMA2(acc0[j], c0.y, n[j].y, acc0[j]);
            }
            #pragma unroll
            for (int j = 0; j < 4; j++) {
                FMA2(acc1[j], c1.x, n[j].x, acc1[j]);
                FMA2(acc1[j], c1.y, n[j].y, acc1[j]);
            }
        }

        // epilogue: batch the 4 butterflies (ILP) instead of 4 serial chains
        float h0[4], h1[4], part[4];
        #pragma unroll
        for (int j = 0; j < 4; j++) {
            h0[j] = lo32(acc0[j]) + hi32(acc0[j]);
            h1[j] = lo32(acc1[j]) + hi32(acc1[j]);
            part[j] = h0[j] * nub[warp][sb + j][d0]
                    + (has1 ? h1[j] * nub[warp][sb + j][d1] : 0.f);
        }
        #pragma unroll
        for (int o = 16; o; o >>= 1) {
            #pragma unroll
            for (int j = 0; j < 4; j++)
                part[j] += __shfl_xor_sync(0xffffffffu, part[j], o);
        }
        #pragma unroll
        for (int j = 0; j < 4; j++) {
            const int u = ubase + j;
            float* Hrow = g_H + (size_t)(nidv * N_UNITS + u) * DDIM;
            Hrow[d0] = h0[j];
            if (has1) Hrow[d1] = h1[j];
            if (lane == 0)
                g_LLC[nidv * N_UNITS + u] = logprop[u] - 0.5f * part[j];
        }
    }
}

// ---------------------------------------------------------------------------
// Kernel 2: per-spike responsibilities. One warp per spike.
// Lane l<30 owns e-pair (2l,2l+1): 1 u64 feature load + 10 u64 H loads
// (clamped index, value-masked), 10 packed FMA2 dot partials, batched
// butterfly, softmax, scatter. (unchanged, R9)
// ---------------------------------------------------------------------------
__global__ void __launch_bounds__(256) k_main(const float* __restrict__ features,
                                              const int*   __restrict__ cands,
                                              const int*   __restrict__ nid,
                                              const float* __restrict__ noise_lp)
{
    const int t    = threadIdx.x;
    const int warp = t >> 5;
    const int lane = t & 31;
    const int s    = blockIdx.x * 8 + warp;
    const int li   = lane < 30 ? lane : 29;   // clamped: loads always valid+aligned

    const float nlp = __ldg(noise_lp);
    const u64* xf2 = reinterpret_cast<const u64*>(features + (size_t)s * DDIM);
    u64 x2 = __ldg(&xf2[li]);
    if (lane >= 30) x2 = 0ull;                // value mask; 0 * h == 0

    const int nidv  = __ldg(&nid[s]);
    const int pbase = nidv * N_UNITS;
    const int ucached = (lane < N_CAND) ? __ldg(&cands[s * N_CAND + lane]) : 0;
    const float llc_l = (lane < N_CAND) ? g_LLC[pbase + ucached] : 0.f;

    // issue all 10 H loads before any reduction (high MLP)
    u64 h2[N_CAND];
    #pragma unroll
    for (int c = 0; c < N_CAND; c++) {
        const int u = __shfl_sync(0xffffffffu, ucached, c);
        const u64* H2 = reinterpret_cast<const u64*>(g_H + (size_t)(pbase + u) * DDIM);
        h2[c] = __ldg(&H2[li]);
    }

    float acc[N_CAND];
    #pragma unroll
    for (int c = 0; c < N_CAND; c++) {
        u64 p2 = 0ull;
        FMA2(p2, x2, h2[c], p2);
        acc[c] = lo32(p2) + hi32(p2);
    }

    // batched butterfly: 5 stages, 10 independent values per stage
    #pragma unroll
    for (int o = 16; o; o >>= 1) {
        #pragma unroll
        for (int c = 0; c < N_CAND; c++)
            acc[c] += __shfl_xor_sync(0xffffffffu, acc[c], o);
    }

    // lane c takes acc[c] (static-index select chain; no dynamic reg indexing)
    float myp = acc[0];
    #pragma unroll
    for (int c = 1; c < N_CAND; c++)
        if (lane == c) myp = acc[c];

    float myll = -CUDART_INF_F;
    if (lane < N_CAND) myll = llc_l + myp;
    if (lane == N_CAND) myll = nlp;

    // softmax across lanes 0..10
    float mx = myll;
    #pragma unroll
    for (int o = 16; o; o >>= 1) mx = fmaxf(mx, __shfl_xor_sync(0xffffffffu, mx, o));
    const float ex = (lane <= N_CAND) ? __expf(myll - mx) : 0.f;
    float sm = ex;
    #pragma unroll
    for (int o = 16; o; o >>= 1) sm += __shfl_xor_sync(0xffffffffu, sm, o);

    if (lane < N_CAND) {
        const float qv = ex / sm;
        const int u = ucached;
        const int pos = atomicAdd(&g_cursor[u * CPITCH], 1);
        if (pos < CAP) {
            g_rec[u * CAP + pos] = make_int2(s, __float_as_int(qv));
        }
    }
}

// ---------------------------------------------------------------------------
// Kernel 3: per-unit weighted reduction, RSPLIT=8 blocks per unit (grid 2048).
// 64 slots per unit, 4-record chunks; partials combined in shared, then
// atomicAdd into out (8 colliding adds per address — cheap).
// ---------------------------------------------------------------------------
__global__ void __launch_bounds__(256) k_reduce(const float* __restrict__ features,
                                                float* __restrict__ out)
{
    const int u    = blockIdx.x >> 3;          // RSPLIT == 8
    const int part = blockIdx.x & 7;
    const int t    = threadIdx.x;
    const int warp = t >> 5;
    const int lane = t & 31;
    const int li   = lane < 30 ? lane : 29;
    const bool act = lane < 30;

    int cnt = g_cursor[u * CPITCH];
    if (cnt > CAP) cnt = CAP;

    const int base = u * CAP;
    const int slot = part * 8 + warp;          // 0..63 across the 8 blocks
    u64 a2 = 0ull;
    float ac = 0.f;

    for (int eb = slot * 4; eb < cnt; eb += 64 * 4) {
        // up to 4 independent records per step (uniform broadcast loads)
        int   n[4];
        float q[4];
        #pragma unroll
        for (int i = 0; i < 4; i++) {
            const bool v = (eb + i) < cnt;
            const int2 rec = v ? g_rec[base + eb + i] : make_int2(0, 0);
            n[i] = rec.x;
            q[i] = v ? __int_as_float(rec.y) : 0.f;
        }
        u64 f2[4];
        #pragma unroll
        for (int i = 0; i < 4; i++) {
            const u64* xf2 = reinterpret_cast<const u64*>(features + (size_t)n[i] * DDIM);
            f2[i] = __ldg(&xf2[li]);
        }
        #pragma unroll
        for (int i = 0; i < 4; i++) {
            const unsigned qb = (unsigned)__float_as_int(q[i]);
            const u64 q2 = ((u64)qb << 32) | qb;
            FMA2(a2, q2, f2[i], a2);
            ac += q[i];
        }
    }

    __shared__ float sh[8][OUT_COLS];
    if (act) {
        sh[warp][1 + 2 * lane] = lo32(a2);   // dim 2l   -> col 1+2l
        sh[warp][2 + 2 * lane] = hi32(a2);   // dim 2l+1 -> col 2+2l
    }
    if (lane == 0) sh[warp][0] = ac;         // count column
    __syncthreads();

    if (t < OUT_COLS) {
        float sum = 0.f;
        #pragma unroll
        for (int w2 = 0; w2 < 8; w2++) sum += sh[w2][t];
        atomicAdd(&out[u * OUT_COLS + t], sum);
    }
}

// ---------------------------------------------------------------------------
// Input order: features, mu, Coo_inv, Coo_logdet, log_proportions,
//              noise_log_prop, cands, nid, obs_ix
// Coo_logdet is unused (cancels in the softmax).
// ---------------------------------------------------------------------------
extern "C" void kernel_launch(void* const* d_in, const int* in_sizes, int n_in,
                              void* d_out, int out_size)
{
    const float* features  = (const float*)d_in[0];
    const float* mu        = (const float*)d_in[1];
    const float* Coo_inv   = (const float*)d_in[2];
    const float* logprop   = (const float*)d_in[4];
    const float* noise_lp  = (const float*)d_in[5];
    const int*   cands     = (const int*)d_in[6];
    const int*   nidp      = (const int*)d_in[7];
    const int*   obs_ix    = (const int*)d_in[8];
    float* out = (float*)d_out;

    k_pre<<<N_NEIGHB * 2, 512>>>(mu, Coo_inv, obs_ix, logprop, out);
    k_main<<<N_SPIKES / 8, 256>>>(features, cands, nidp, noise_lp);
    k_reduce<<<N_UNITS * RSPLIT, 256>>>(features, out);
}